// round 16
// baseline (speedup 1.0000x reference)
#include <cuda_runtime.h>
#include <cuda_fp16.h>
#include <math.h>
#include <stdint.h>

// Problem constants (B=2, N=1024 -> T=2048 tokens; D=768; E=8; H=3072; K=2)
#define T_TOK 2048
#define D_DIM 768
#define E_EXP 8
#define H_DIM 3072

// ---------------------------------------------------------------------------
// Static device scratch (allocation-free per harness rules)
// ---------------------------------------------------------------------------
__device__ int    g_count[E_EXP];
__device__ int    g_tok[E_EXP * T_TOK];
__device__ int    g_np[T_TOK];
__device__ int    g_te[T_TOK * E_EXP];
__device__ int    g_ts[T_TOK * E_EXP];
__device__ __half g_hh[(size_t)E_EXP * T_TOK * H_DIM];    // gelu(gate)*value, fp16
__device__ __half g_y[(size_t)E_EXP * T_TOK * D_DIM];     // expert out, K-half 0
__device__ __half g_y2[(size_t)E_EXP * T_TOK * D_DIM];    // expert out, K-half 1
__device__ __half g_xh[(size_t)T_TOK * D_DIM];            // fp16 tokens
__device__ __half g_wgh[(size_t)E_EXP * H_DIM * D_DIM];   // fp16 Wg
__device__ __half g_wvh[(size_t)E_EXP * H_DIM * D_DIM];   // fp16 Wv
__device__ __half g_woh[(size_t)E_EXP * D_DIM * H_DIM];   // fp16 Wo * scale_e

// ---------------------------------------------------------------------------
// PTX helpers (family-generic: mma.sync sm80+, ldmatrix sm75+, cp.async sm80+)
// ---------------------------------------------------------------------------
#define MMA_F16(d, a, b)                                                         \
    asm volatile("mma.sync.aligned.m16n8k16.row.col.f32.f16.f16.f32 "            \
        "{%0,%1,%2,%3},{%4,%5,%6,%7},{%8,%9},{%0,%1,%2,%3};"                     \
        : "+f"((d)[0]), "+f"((d)[1]), "+f"((d)[2]), "+f"((d)[3])                  \
        : "r"((a)[0]), "r"((a)[1]), "r"((a)[2]), "r"((a)[3]),                     \
          "r"((b)[0]), "r"((b)[1]))

#define LDSM4(r, addr)                                                           \
    asm volatile("ldmatrix.sync.aligned.m8n8.x4.shared.b16 {%0,%1,%2,%3}, [%4];" \
        : "=r"((r)[0]), "=r"((r)[1]), "=r"((r)[2]), "=r"((r)[3]) : "r"(addr))

#define CP16(dst, src)                                                           \
    asm volatile("cp.async.cg.shared.global [%0], [%1], 16;"                     \
        :: "r"(dst), "l"(src))
#define CP16Z(dst, src, sz)                                                      \
    asm volatile("cp.async.cg.shared.global [%0], [%1], 16, %2;"                 \
        :: "r"(dst), "l"(src), "r"(sz))
#define CP_COMMIT() asm volatile("cp.async.commit_group;" ::: "memory")
#define CP_WAIT0()  asm volatile("cp.async.wait_group 0;" ::: "memory")
#define CP_WAIT1()  asm volatile("cp.async.wait_group 1;" ::: "memory")

__device__ __forceinline__ uint32_t sm_addr(const void* p) {
    return (uint32_t)__cvta_generic_to_shared(p);
}

// ---------------------------------------------------------------------------
// Routing build (verified R1)
// ---------------------------------------------------------------------------
__global__ void zero_counts_kernel() {
    int i = threadIdx.x;
    if (i < E_EXP) g_count[i] = 0;
}

__global__ void build_kernel(const float* __restrict__ disp) {
    int t = blockIdx.x * blockDim.x + threadIdx.x;
    if (t >= T_TOK) return;
    int np = 0;
#pragma unroll
    for (int e = 0; e < E_EXP; e++) {
        if (disp[t * E_EXP + e] > 0.0f) {
            int s = atomicAdd(&g_count[e], 1);
            g_tok[e * T_TOK + s] = t;
            g_te[t * E_EXP + np] = e;
            g_ts[t * E_EXP + np] = s;
            np++;
        }
    }
    g_np[t] = np;
}

// ---------------------------------------------------------------------------
// fp32 -> fp16 conversion, 4 float4 per thread (64B contiguous per thread).
// Main stream: tokens + Wg + Wv. Wo on side stream, overlapping gemm1.
// ---------------------------------------------------------------------------
#define X4  (T_TOK * D_DIM / 4)            // 393216
#define W4  (E_EXP * H_DIM * D_DIM / 4)    // 4718592
#define EW4 (D_DIM * H_DIM / 4)            // 589824 (per-expert Wo float4s)
#define NTOT4 (X4 + 2 * W4)                // 9830400 (divisible by 4)

__global__ void cvt_main_kernel(const float4* __restrict__ tok,
                                const float4* __restrict__ wg,
                                const float4* __restrict__ wv,
                                uint2* __restrict__ xh, uint2* __restrict__ wgh,
                                uint2* __restrict__ wvh)
{
    int base = (blockIdx.x * blockDim.x + threadIdx.x) * 4;
#pragma unroll
    for (int u = 0; u < 4; u++) {
        int i = base + u;
        if (i >= NTOT4) return;
        float4 f; uint2* dst;
        if (i < X4)            { f = tok[i];            dst = xh  + i; }
        else {
            int j = i - X4;
            if (j < W4)        { f = wg[j];             dst = wgh + j; }
            else               { j -= W4; f = wv[j];    dst = wvh + j; }
        }
        __half2 h01 = __floats2half2_rn(f.x, f.y);
        __half2 h23 = __floats2half2_rn(f.z, f.w);
        uint2 o;
        o.x = *(const uint32_t*)&h01;
        o.y = *(const uint32_t*)&h23;
        *dst = o;
    }
}

__global__ void cvt_wo_kernel(const float4* __restrict__ wo,
                              const float*  __restrict__ scale,
                              uint2* __restrict__ woh)
{
    int base = (blockIdx.x * blockDim.x + threadIdx.x) * 4;
#pragma unroll
    for (int u = 0; u < 4; u++) {
        int j = base + u;
        if (j >= W4) return;
        float sc = scale[j / EW4];
        float4 f = wo[j];
        __half2 h01 = __floats2half2_rn(f.x * sc, f.y * sc);
        __half2 h23 = __floats2half2_rn(f.z * sc, f.w * sc);
        uint2 o;
        o.x = *(const uint32_t*)&h01;
        o.y = *(const uint32_t*)&h23;
        woh[j] = o;
    }
}

// ---------------------------------------------------------------------------
// Tiling (R12/R14 config): block 128(m) x 64(n), 256 threads, 8 warps
// (4m x 2n), warp 32x32. KC = 64 halves, PH = 72. 3-stage ring. 2 CTAs/SM.
// Grid.x = 16 m-tiles; inactive tiles exit immediately (proven-best packing).
// ---------------------------------------------------------------------------
#define KC     64
#define PH     72
#define ROWB   (PH * 2)             // 144 B
#define STAGES 3
#define AOFFB  0
#define GOFFB  (128 * ROWB)         // 18432
#define VOFFB  (192 * ROWB)         // 27648
#define BUF1B  (256 * ROWB)         // 36864 B (A128 + G64 + V64)
#define SMEM1  (STAGES * BUF1B)     // 110592 B
#define BOFFB  (128 * ROWB)         // gemm2: B rows after 128 A rows
#define BUF2B  (192 * ROWB)         // 27648 B (A128 + B64)
#define SMEM2  (STAGES * BUF2B)     // 82944 B

// ---------------------------------------------------------------------------
// Stage 1: gate = X@Wg^T, value = X@Wv^T (fp16 mma), fused GELU epilogue.
// Grid (16, 48, 8); inactive m-tiles exit.
// ---------------------------------------------------------------------------
__global__ __launch_bounds__(256, 2) void gemm1_tc()
{
    extern __shared__ __half smh[];
    const int e   = blockIdx.z;
    const int cnt = g_count[e];
    const int m0  = blockIdx.x * 128;
    if (m0 >= cnt) return;
    const int n0  = blockIdx.y * 64;

    const int tid  = threadIdx.x;
    const int lane = tid & 31;
    const int wid  = tid >> 5;
    const int wm   = wid >> 1;        // 0..3
    const int wn   = wid & 1;         // 0..1
    const int g    = lane >> 2;       // 0..7
    const int tg   = lane & 3;        // 0..3

    const int seg = tid & 7;          // 16B segment within 128B of K
    const int rr  = tid >> 3;         // 0..31
    const uint32_t sb = sm_addr(smh);
    const size_t ew = (size_t)e * H_DIM * D_DIM;

    const __half* xsrc[4]; uint32_t xsz[4]; uint32_t xdst[4];
#pragma unroll
    for (int i = 0; i < 4; i++) {
        int r    = rr + 32 * i;       // 0..127
        int slot = m0 + r;
        bool v   = slot < cnt;
        int tok  = v ? g_tok[e * T_TOK + slot] : 0;
        xsrc[i]  = g_xh + (size_t)tok * D_DIM + seg * 8;
        xsz[i]   = v ? 16u : 0u;
        xdst[i]  = AOFFB + (uint32_t)(r * PH + seg * 8) * 2u;
    }
    const __half* gsrc[2]; const __half* vsrc[2]; uint32_t wdst[2];
#pragma unroll
    for (int i = 0; i < 2; i++) {
        int r   = rr + 32 * i;        // 0..63 (weight rows)
        gsrc[i] = g_wgh + ew + (size_t)(n0 + r) * D_DIM + seg * 8;
        vsrc[i] = g_wvh + ew + (size_t)(n0 + r) * D_DIM + seg * 8;
        wdst[i] = (uint32_t)(r * PH + seg * 8) * 2u;
    }

#define G1_LOAD(slot, k0) do {                                                   \
    uint32_t _b = sb + (uint32_t)(slot) * BUF1B;                                  \
    _Pragma("unroll")                                                             \
    for (int i = 0; i < 4; i++)                                                   \
        CP16Z(_b + xdst[i], (xsrc[i] + (k0)), xsz[i]);                            \
    _Pragma("unroll")                                                             \
    for (int i = 0; i < 2; i++) {                                                 \
        CP16(_b + GOFFB + wdst[i], (gsrc[i] + (k0)));                             \
        CP16(_b + VOFFB + wdst[i], (vsrc[i] + (k0)));                             \
    }                                                                             \
    CP_COMMIT();                                                                  \
} while (0)

    const uint32_t aoff = (uint32_t)((wm * 32 + (lane & 15)) * PH
                                     + ((lane >> 4) * 8)) * 2u;
    const uint32_t boff = (uint32_t)((wn * 32 + ((lane >> 4) * 8) + (lane & 7)) * PH
                                     + (((lane >> 3) & 1) * 8)) * 2u;

    float accg[2][4][4] = {};
    float accv[2][4][4] = {};

    const int NIT = D_DIM / KC;   // 12
    G1_LOAD(0, 0);
    G1_LOAD(1, KC);

    int slot = 0;
#pragma unroll 1
    for (int it = 0; it < NIT; ++it) {
        if (it < NIT - 1) CP_WAIT1(); else CP_WAIT0();
        __syncthreads();

        if (it + 2 < NIT) {
            int ns = slot + 2; if (ns >= STAGES) ns -= STAGES;
            G1_LOAD(ns, (it + 2) * KC);
        }

        const uint32_t ba = sb + (uint32_t)slot * BUF1B;
        const uint32_t Xa = ba + aoff;
        const uint32_t Ga = ba + GOFFB + boff;
        const uint32_t Va = ba + VOFFB + boff;
#pragma unroll
        for (int ks = 0; ks < 4; ks++) {
            const uint32_t kb = ks * 32;           // 16 halves = 32 bytes
            uint32_t a[2][4];
#pragma unroll
            for (int fm = 0; fm < 2; fm++)
                LDSM4(a[fm], Xa + fm * (16 * ROWB) + kb);
#pragma unroll
            for (int fp = 0; fp < 2; fp++) {       // fn pairs
                uint32_t bg[4], bv[4];
                LDSM4(bg, Ga + fp * (16 * ROWB) + kb);
                LDSM4(bv, Va + fp * (16 * ROWB) + kb);
#pragma unroll
                for (int fm = 0; fm < 2; fm++) {
                    MMA_F16(accg[fm][2 * fp],     a[fm], (bg + 0));
                    MMA_F16(accg[fm][2 * fp + 1], a[fm], (bg + 2));
                    MMA_F16(accv[fm][2 * fp],     a[fm], (bv + 0));
                    MMA_F16(accv[fm][2 * fp + 1], a[fm], (bv + 2));
                }
            }
        }
        slot++; if (slot >= STAGES) slot -= STAGES;
    }

    // ---- epilogue: h = gelu(gate) * value -> fp16 ----
#pragma unroll
    for (int fm = 0; fm < 2; fm++) {
        int r0 = m0 + wm * 32 + fm * 16 + g;
        int r1 = r0 + 8;
        __half* h0 = g_hh + ((size_t)e * T_TOK + r0) * H_DIM;
        __half* h1 = g_hh + ((size_t)e * T_TOK + r1) * H_DIM;
        bool v0 = r0 < cnt, v1 = r1 < cnt;
#pragma unroll
        for (int fn = 0; fn < 4; fn++) {
            int c = n0 + wn * 32 + fn * 8 + 2 * tg;
            if (v0) {
                float ga = accg[fm][fn][0], gb = accg[fm][fn][1];
                float oa = 0.5f * ga * (1.0f + erff(ga * 0.70710678118654752f))
                         * accv[fm][fn][0];
                float ob = 0.5f * gb * (1.0f + erff(gb * 0.70710678118654752f))
                         * accv[fm][fn][1];
                *(__half2*)(h0 + c) = __floats2half2_rn(oa, ob);
            }
            if (v1) {
                float ga = accg[fm][fn][2], gb = accg[fm][fn][3];
                float oa = 0.5f * ga * (1.0f + erff(ga * 0.70710678118654752f))
                         * accv[fm][fn][2];
                float ob = 0.5f * gb * (1.0f + erff(gb * 0.70710678118654752f))
                         * accv[fm][fn][3];
                *(__half2*)(h1 + c) = __floats2half2_rn(oa, ob);
            }
        }
    }
}

// ---------------------------------------------------------------------------
// Stage 2: y = h @ (Wo*scale)^T, split-K x2 (separate buffers, deterministic).
// Block 128m x 64n. blockIdx.z = e*2 + khalf. Grid (16, 12, 16). fp16 out.
// ---------------------------------------------------------------------------
__global__ __launch_bounds__(256, 2) void gemm2_tc()
{
    extern __shared__ __half smh[];
    const int e     = blockIdx.z >> 1;
    const int kh    = blockIdx.z & 1;
    const int cnt   = g_count[e];
    const int m0    = blockIdx.x * 128;
    if (m0 >= cnt) return;
    const int n0    = blockIdx.y * 64;
    const int kbase = kh * (H_DIM / 2);

    const int tid  = threadIdx.x;
    const int lane = tid & 31;
    const int wid  = tid >> 5;
    const int wm   = wid >> 1;
    const int wn   = wid & 1;
    const int g    = lane >> 2;
    const int tg   = lane & 3;

    const int seg = tid & 7;
    const int rr  = tid >> 3;         // 0..31
    const uint32_t sb = sm_addr(smh);
    const size_t ewo = (size_t)e * D_DIM * H_DIM;

    const __half* asrc[4]; uint32_t asz[4]; uint32_t adst[4];
#pragma unroll
    for (int i = 0; i < 4; i++) {
        int r    = rr + 32 * i;
        int slot = m0 + r;
        bool v   = slot < cnt;
        asrc[i]  = g_hh + ((size_t)e * T_TOK + (v ? slot : 0)) * H_DIM
                 + kbase + seg * 8;
        asz[i]   = v ? 16u : 0u;
        adst[i]  = (uint32_t)(r * PH + seg * 8) * 2u;
    }
    const __half* bsrc[2]; uint32_t bdst[2];
#pragma unroll
    for (int i = 0; i < 2; i++) {
        int r   = rr + 32 * i;        // 0..63
        bsrc[i] = g_woh + ewo + (size_t)(n0 + r) * H_DIM + kbase + seg * 8;
        bdst[i] = (uint32_t)(r * PH + seg * 8) * 2u;
    }

#define G2_LOAD(slot, k0) do {                                                   \
    uint32_t _b = sb + (uint32_t)(slot) * BUF2B;                                  \
    _Pragma("unroll")                                                             \
    for (int i = 0; i < 4; i++)                                                   \
        CP16Z(_b + adst[i], (asrc[i] + (k0)), asz[i]);                            \
    _Pragma("unroll")                                                             \
    for (int i = 0; i < 2; i++)                                                   \
        CP16(_b + BOFFB + bdst[i], (bsrc[i] + (k0)));                             \
    CP_COMMIT();                                                                  \
} while (0)

    const uint32_t aoff = (uint32_t)((wm * 32 + (lane & 15)) * PH
                                     + ((lane >> 4) * 8)) * 2u;
    const uint32_t boff = (uint32_t)((wn * 32 + ((lane >> 4) * 8) + (lane & 7)) * PH
                                     + (((lane >> 3) & 1) * 8)) * 2u;

    float acc[2][4][4] = {};

    const int NIT = (H_DIM / 2) / KC;   // 24
    G2_LOAD(0, 0);
    G2_LOAD(1, KC);

    int slot = 0;
#pragma unroll 1
    for (int it = 0; it < NIT; ++it) {
        if (it < NIT - 1) CP_WAIT1(); else CP_WAIT0();
        __syncthreads();

        if (it + 2 < NIT) {
            int ns = slot + 2; if (ns >= STAGES) ns -= STAGES;
            G2_LOAD(ns, (it + 2) * KC);
        }

        const uint32_t ba = sb + (uint32_t)slot * BUF2B;
        const uint32_t Aa = ba + aoff;
        const uint32_t Ba = ba + BOFFB + boff;
#pragma unroll
        for (int ks = 0; ks < 4; ks++) {
            const uint32_t kb = ks * 32;
            uint32_t a[2][4];
#pragma unroll
            for (int fm = 0; fm < 2; fm++)
                LDSM4(a[fm], Aa + fm * (16 * ROWB) + kb);
#pragma unroll
            for (int fp = 0; fp < 2; fp++) {
                uint32_t b[4];
                LDSM4(b, Ba + fp * (16 * ROWB) + kb);
#pragma unroll
                for (int fm = 0; fm < 2; fm++) {
                    MMA_F16(acc[fm][2 * fp],     a[fm], (b + 0));
                    MMA_F16(acc[fm][2 * fp + 1], a[fm], (b + 2));
                }
            }
        }
        slot++; if (slot >= STAGES) slot -= STAGES;
    }

    __half* ybuf = kh ? g_y2 : g_y;
#pragma unroll
    for (int fm = 0; fm < 2; fm++) {
        int r0 = m0 + wm * 32 + fm * 16 + g;
        int r1 = r0 + 8;
        __half* y0 = ybuf + ((size_t)e * T_TOK + r0) * D_DIM;
        __half* y1 = ybuf + ((size_t)e * T_TOK + r1) * D_DIM;
        bool v0 = r0 < cnt, v1 = r1 < cnt;
#pragma unroll
        for (int fn = 0; fn < 4; fn++) {
            int c = n0 + wn * 32 + fn * 8 + 2 * tg;
            if (v0) *(__half2*)(y0 + c) =
                __floats2half2_rn(acc[fm][fn][0], acc[fm][fn][1]);
            if (v1) *(__half2*)(y1 + c) =
                __floats2half2_rn(acc[fm][fn][2], acc[fm][fn][3]);
        }
    }
}

// ---------------------------------------------------------------------------
// Combine -> d_out. 4 elements per thread (uint2 loads = 4 halves per buffer,
// two float2 stores). fp32 accumulation, single deterministic write/element.
// ---------------------------------------------------------------------------
__global__ void combine_kernel(const float* __restrict__ comb,
                               float* __restrict__ out)
{
    int idx = blockIdx.x * blockDim.x + threadIdx.x;   // over T*D/4
    if (idx >= T_TOK * (D_DIM / 4)) return;
    int t  = idx / (D_DIM / 4);
    int d4 = idx - t * (D_DIM / 4);
    float4 acc = make_float4(0.0f, 0.0f, 0.0f, 0.0f);
    int np = g_np[t];
    for (int j = 0; j < np; j++) {
        int e = g_te[t * E_EXP + j];
        int s = g_ts[t * E_EXP + j];
        size_t o = ((size_t)e * T_TOK + s) * (D_DIM / 4) + d4;
        uint2 ua = *((const uint2*)g_y  + o);
        uint2 ub = *((const uint2*)g_y2 + o);
        float2 a0 = __half22float2(*(const __half2*)&ua.x);
        float2 a1 = __half22float2(*(const __half2*)&ua.y);
        float2 b0 = __half22float2(*(const __half2*)&ub.x);
        float2 b1 = __half22float2(*(const __half2*)&ub.y);
        float  w  = comb[t * E_EXP + e];
        acc.x += w * (a0.x + b0.x);
        acc.y += w * (a0.y + b0.y);
        acc.z += w * (a1.x + b1.x);
        acc.w += w * (a1.y + b1.y);
    }
    ((float2*)out)[idx * 2]     = make_float2(acc.x, acc.y);
    ((float2*)out)[idx * 2 + 1] = make_float2(acc.z, acc.w);
}

// ---------------------------------------------------------------------------
// Launch (R14 skeleton). Side stream: zero+build overlap cvt_main; Wo cvt
// overlaps gemm1. Full-width GEMMs (no expert/m fragmentation).
// ---------------------------------------------------------------------------
extern "C" void kernel_launch(void* const* d_in, const int* in_sizes, int n_in,
                              void* d_out, int out_size)
{
    const float* tokens = (const float*)d_in[0];
    const float* disp   = (const float*)d_in[1];
    const float* comb   = (const float*)d_in[2];
    const float* Wg     = (const float*)d_in[3];
    const float* Wv     = (const float*)d_in[4];
    const float* Wo     = (const float*)d_in[5];
    const float* scale  = (const float*)d_in[6];
    float* out = (float*)d_out;

    static cudaStream_t s2 = nullptr;
    static cudaEvent_t evS = nullptr, evB = nullptr, evF = nullptr, evJ = nullptr;
    if (!s2) {
        cudaStreamCreateWithFlags(&s2, cudaStreamNonBlocking);
        cudaEventCreateWithFlags(&evS, cudaEventDisableTiming);
        cudaEventCreateWithFlags(&evB, cudaEventDisableTiming);
        cudaEventCreateWithFlags(&evF, cudaEventDisableTiming);
        cudaEventCreateWithFlags(&evJ, cudaEventDisableTiming);
        cudaFuncSetAttribute(gemm1_tc, cudaFuncAttributeMaxDynamicSharedMemorySize, SMEM1);
        cudaFuncSetAttribute(gemm2_tc, cudaFuncAttributeMaxDynamicSharedMemorySize, SMEM2);
    }

    __half* xh;  cudaGetSymbolAddress((void**)&xh,  g_xh);
    __half* wgh; cudaGetSymbolAddress((void**)&wgh, g_wgh);
    __half* wvh; cudaGetSymbolAddress((void**)&wvh, g_wvh);
    __half* woh; cudaGetSymbolAddress((void**)&woh, g_woh);

    // Fork at start: side stream runs routing build while main runs cvt_main.
    cudaEventRecord(evS, 0);
    cudaStreamWaitEvent(s2, evS, 0);
    zero_counts_kernel<<<1, 32, 0, s2>>>();
    build_kernel<<<(T_TOK + 255) / 256, 256, 0, s2>>>(disp);
    cudaEventRecord(evB, s2);

    cvt_main_kernel<<<(NTOT4 / 4 + 255) / 256, 256>>>(
        (const float4*)tokens, (const float4*)Wg, (const float4*)Wv,
        (uint2*)xh, (uint2*)wgh, (uint2*)wvh);

    // Wo conversion on side stream (after build), overlapping gemm1.
    cudaEventRecord(evF, 0);
    cudaStreamWaitEvent(s2, evF, 0);
    cvt_wo_kernel<<<(W4 / 4 + 255) / 256, 256, 0, s2>>>(
        (const float4*)Wo, scale, (uint2*)woh);
    cudaEventRecord(evJ, s2);

    // gemm1 needs build (g_tok/g_count) + cvt_main.
    cudaStreamWaitEvent(0, evB, 0);
    dim3 g1(T_TOK / 128, H_DIM / 64, E_EXP);        // (16, 48, 8)
    gemm1_tc<<<g1, 256, SMEM1>>>();

    // gemm2 needs woh.
    cudaStreamWaitEvent(0, evJ, 0);
    dim3 g2(T_TOK / 128, D_DIM / 64, 2 * E_EXP);    // (16, 12, 16) split-K
    gemm2_tc<<<g2, 256, SMEM2>>>();

    combine_kernel<<<(T_TOK * D_DIM / 4 + 255) / 256, 256>>>(comb, out);
}

// round 17
// speedup vs baseline: 1.0736x; 1.0736x over previous
#include <cuda_runtime.h>
#include <cuda_fp16.h>
#include <math.h>
#include <stdint.h>

// Problem constants (B=2, N=1024 -> T=2048 tokens; D=768; E=8; H=3072; K=2)
#define T_TOK 2048
#define D_DIM 768
#define E_EXP 8
#define H_DIM 3072

// ---------------------------------------------------------------------------
// Static device scratch (allocation-free per harness rules)
// ---------------------------------------------------------------------------
__device__ int    g_count[E_EXP];
__device__ int    g_tok[E_EXP * T_TOK];
__device__ int    g_np[T_TOK];
__device__ int    g_te[T_TOK * E_EXP];
__device__ int    g_ts[T_TOK * E_EXP];
__device__ __half g_hh[(size_t)E_EXP * T_TOK * H_DIM];    // gelu(gate)*value, fp16
__device__ __half g_y[(size_t)E_EXP * T_TOK * D_DIM];     // expert out, K-half 0
__device__ __half g_y2[(size_t)E_EXP * T_TOK * D_DIM];    // expert out, K-half 1
__device__ __half g_xh[(size_t)T_TOK * D_DIM];            // fp16 tokens
__device__ __half g_wgh[(size_t)E_EXP * H_DIM * D_DIM];   // fp16 Wg
__device__ __half g_wvh[(size_t)E_EXP * H_DIM * D_DIM];   // fp16 Wv
__device__ __half g_woh[(size_t)E_EXP * D_DIM * H_DIM];   // fp16 Wo * scale_e

// ---------------------------------------------------------------------------
// PTX helpers (family-generic: mma.sync sm80+, ldmatrix sm75+, cp.async sm80+)
// ---------------------------------------------------------------------------
#define MMA_F16(d, a, b)                                                         \
    asm volatile("mma.sync.aligned.m16n8k16.row.col.f32.f16.f16.f32 "            \
        "{%0,%1,%2,%3},{%4,%5,%6,%7},{%8,%9},{%0,%1,%2,%3};"                     \
        : "+f"((d)[0]), "+f"((d)[1]), "+f"((d)[2]), "+f"((d)[3])                  \
        : "r"((a)[0]), "r"((a)[1]), "r"((a)[2]), "r"((a)[3]),                     \
          "r"((b)[0]), "r"((b)[1]))

#define LDSM4(r, addr)                                                           \
    asm volatile("ldmatrix.sync.aligned.m8n8.x4.shared.b16 {%0,%1,%2,%3}, [%4];" \
        : "=r"((r)[0]), "=r"((r)[1]), "=r"((r)[2]), "=r"((r)[3]) : "r"(addr))

#define CP16(dst, src)                                                           \
    asm volatile("cp.async.cg.shared.global [%0], [%1], 16;"                     \
        :: "r"(dst), "l"(src))
#define CP16Z(dst, src, sz)                                                      \
    asm volatile("cp.async.cg.shared.global [%0], [%1], 16, %2;"                 \
        :: "r"(dst), "l"(src), "r"(sz))
#define CP_COMMIT() asm volatile("cp.async.commit_group;" ::: "memory")
#define CP_WAIT0()  asm volatile("cp.async.wait_group 0;" ::: "memory")
#define CP_WAIT1()  asm volatile("cp.async.wait_group 1;" ::: "memory")

__device__ __forceinline__ uint32_t sm_addr(const void* p) {
    return (uint32_t)__cvta_generic_to_shared(p);
}

// ---------------------------------------------------------------------------
// Routing build (verified R1)
// ---------------------------------------------------------------------------
__global__ void zero_counts_kernel() {
    int i = threadIdx.x;
    if (i < E_EXP) g_count[i] = 0;
}

__global__ void build_kernel(const float* __restrict__ disp) {
    int t = blockIdx.x * blockDim.x + threadIdx.x;
    if (t >= T_TOK) return;
    int np = 0;
#pragma unroll
    for (int e = 0; e < E_EXP; e++) {
        if (disp[t * E_EXP + e] > 0.0f) {
            int s = atomicAdd(&g_count[e], 1);
            g_tok[e * T_TOK + s] = t;
            g_te[t * E_EXP + np] = e;
            g_ts[t * E_EXP + np] = s;
            np++;
        }
    }
    g_np[t] = np;
}

// ---------------------------------------------------------------------------
// fp32 -> fp16 conversion, 2 float4 per thread (R13/R14-proven optimum).
// Main stream: tokens + Wg + Wv. Wo on side stream, overlapping gemm1.
// ---------------------------------------------------------------------------
#define X4  (T_TOK * D_DIM / 4)            // 393216
#define W4  (E_EXP * H_DIM * D_DIM / 4)    // 4718592
#define EW4 (D_DIM * H_DIM / 4)            // 589824 (per-expert Wo float4s)
#define NTOT4 (X4 + 2 * W4)                // 9830400 (even)

__global__ void cvt_main_kernel(const float4* __restrict__ tok,
                                const float4* __restrict__ wg,
                                const float4* __restrict__ wv,
                                uint2* __restrict__ xh, uint2* __restrict__ wgh,
                                uint2* __restrict__ wvh)
{
    int base = (blockIdx.x * blockDim.x + threadIdx.x) * 2;
#pragma unroll
    for (int u = 0; u < 2; u++) {
        int i = base + u;
        if (i >= NTOT4) return;
        float4 f; uint2* dst;
        if (i < X4)            { f = tok[i];            dst = xh  + i; }
        else {
            int j = i - X4;
            if (j < W4)        { f = wg[j];             dst = wgh + j; }
            else               { j -= W4; f = wv[j];    dst = wvh + j; }
        }
        __half2 h01 = __floats2half2_rn(f.x, f.y);
        __half2 h23 = __floats2half2_rn(f.z, f.w);
        uint2 o;
        o.x = *(const uint32_t*)&h01;
        o.y = *(const uint32_t*)&h23;
        *dst = o;
    }
}

__global__ void cvt_wo_kernel(const float4* __restrict__ wo,
                              const float*  __restrict__ scale,
                              uint2* __restrict__ woh)
{
    int base = (blockIdx.x * blockDim.x + threadIdx.x) * 2;
#pragma unroll
    for (int u = 0; u < 2; u++) {
        int j = base + u;
        if (j >= W4) return;
        float sc = scale[j / EW4];
        float4 f = wo[j];
        __half2 h01 = __floats2half2_rn(f.x * sc, f.y * sc);
        __half2 h23 = __floats2half2_rn(f.z * sc, f.w * sc);
        uint2 o;
        o.x = *(const uint32_t*)&h01;
        o.y = *(const uint32_t*)&h23;
        woh[j] = o;
    }
}

// ---------------------------------------------------------------------------
// Tiling (R12/R14 config): block 128(m) x 64(n), 256 threads, 8 warps
// (4m x 2n), warp 32x32. KC = 64 halves, PH = 72. 3-stage ring. 2 CTAs/SM.
// Grid.x = 16 m-tiles; inactive tiles exit immediately (proven-best packing).
// ---------------------------------------------------------------------------
#define KC     64
#define PH     72
#define ROWB   (PH * 2)             // 144 B
#define STAGES 3
#define AOFFB  0
#define GOFFB  (128 * ROWB)         // 18432
#define VOFFB  (192 * ROWB)         // 27648
#define BUF1B  (256 * ROWB)         // 36864 B (A128 + G64 + V64)
#define SMEM1  (STAGES * BUF1B)     // 110592 B
#define BOFFB  (128 * ROWB)         // gemm2: B rows after 128 A rows
#define BUF2B  (192 * ROWB)         // 27648 B (A128 + B64)
#define SMEM2  (STAGES * BUF2B)     // 82944 B

// ---------------------------------------------------------------------------
// Stage 1: gate = X@Wg^T, value = X@Wv^T (fp16 mma), fused GELU epilogue.
// Grid (16, 48, 8); inactive m-tiles exit.
// ---------------------------------------------------------------------------
__global__ __launch_bounds__(256, 2) void gemm1_tc()
{
    extern __shared__ __half smh[];
    const int e   = blockIdx.z;
    const int cnt = g_count[e];
    const int m0  = blockIdx.x * 128;
    if (m0 >= cnt) return;
    const int n0  = blockIdx.y * 64;

    const int tid  = threadIdx.x;
    const int lane = tid & 31;
    const int wid  = tid >> 5;
    const int wm   = wid >> 1;        // 0..3
    const int wn   = wid & 1;         // 0..1
    const int g    = lane >> 2;       // 0..7
    const int tg   = lane & 3;        // 0..3

    const int seg = tid & 7;          // 16B segment within 128B of K
    const int rr  = tid >> 3;         // 0..31
    const uint32_t sb = sm_addr(smh);
    const size_t ew = (size_t)e * H_DIM * D_DIM;

    const __half* xsrc[4]; uint32_t xsz[4]; uint32_t xdst[4];
#pragma unroll
    for (int i = 0; i < 4; i++) {
        int r    = rr + 32 * i;       // 0..127
        int slot = m0 + r;
        bool v   = slot < cnt;
        int tok  = v ? g_tok[e * T_TOK + slot] : 0;
        xsrc[i]  = g_xh + (size_t)tok * D_DIM + seg * 8;
        xsz[i]   = v ? 16u : 0u;
        xdst[i]  = AOFFB + (uint32_t)(r * PH + seg * 8) * 2u;
    }
    const __half* gsrc[2]; const __half* vsrc[2]; uint32_t wdst[2];
#pragma unroll
    for (int i = 0; i < 2; i++) {
        int r   = rr + 32 * i;        // 0..63 (weight rows)
        gsrc[i] = g_wgh + ew + (size_t)(n0 + r) * D_DIM + seg * 8;
        vsrc[i] = g_wvh + ew + (size_t)(n0 + r) * D_DIM + seg * 8;
        wdst[i] = (uint32_t)(r * PH + seg * 8) * 2u;
    }

#define G1_LOAD(slot, k0) do {                                                   \
    uint32_t _b = sb + (uint32_t)(slot) * BUF1B;                                  \
    _Pragma("unroll")                                                             \
    for (int i = 0; i < 4; i++)                                                   \
        CP16Z(_b + xdst[i], (xsrc[i] + (k0)), xsz[i]);                            \
    _Pragma("unroll")                                                             \
    for (int i = 0; i < 2; i++) {                                                 \
        CP16(_b + GOFFB + wdst[i], (gsrc[i] + (k0)));                             \
        CP16(_b + VOFFB + wdst[i], (vsrc[i] + (k0)));                             \
    }                                                                             \
    CP_COMMIT();                                                                  \
} while (0)

    const uint32_t aoff = (uint32_t)((wm * 32 + (lane & 15)) * PH
                                     + ((lane >> 4) * 8)) * 2u;
    const uint32_t boff = (uint32_t)((wn * 32 + ((lane >> 4) * 8) + (lane & 7)) * PH
                                     + (((lane >> 3) & 1) * 8)) * 2u;

    float accg[2][4][4] = {};
    float accv[2][4][4] = {};

    const int NIT = D_DIM / KC;   // 12
    G1_LOAD(0, 0);
    G1_LOAD(1, KC);

    int slot = 0;
#pragma unroll 1
    for (int it = 0; it < NIT; ++it) {
        if (it < NIT - 1) CP_WAIT1(); else CP_WAIT0();
        __syncthreads();

        if (it + 2 < NIT) {
            int ns = slot + 2; if (ns >= STAGES) ns -= STAGES;
            G1_LOAD(ns, (it + 2) * KC);
        }

        const uint32_t ba = sb + (uint32_t)slot * BUF1B;
        const uint32_t Xa = ba + aoff;
        const uint32_t Ga = ba + GOFFB + boff;
        const uint32_t Va = ba + VOFFB + boff;
#pragma unroll
        for (int ks = 0; ks < 4; ks++) {
            const uint32_t kb = ks * 32;           // 16 halves = 32 bytes
            uint32_t a[2][4];
#pragma unroll
            for (int fm = 0; fm < 2; fm++)
                LDSM4(a[fm], Xa + fm * (16 * ROWB) + kb);
#pragma unroll
            for (int fp = 0; fp < 2; fp++) {       // fn pairs
                uint32_t bg[4], bv[4];
                LDSM4(bg, Ga + fp * (16 * ROWB) + kb);
                LDSM4(bv, Va + fp * (16 * ROWB) + kb);
#pragma unroll
                for (int fm = 0; fm < 2; fm++) {
                    MMA_F16(accg[fm][2 * fp],     a[fm], (bg + 0));
                    MMA_F16(accg[fm][2 * fp + 1], a[fm], (bg + 2));
                    MMA_F16(accv[fm][2 * fp],     a[fm], (bv + 0));
                    MMA_F16(accv[fm][2 * fp + 1], a[fm], (bv + 2));
                }
            }
        }
        slot++; if (slot >= STAGES) slot -= STAGES;
    }

    // ---- epilogue: h = gelu(gate) * value -> fp16 ----
#pragma unroll
    for (int fm = 0; fm < 2; fm++) {
        int r0 = m0 + wm * 32 + fm * 16 + g;
        int r1 = r0 + 8;
        __half* h0 = g_hh + ((size_t)e * T_TOK + r0) * H_DIM;
        __half* h1 = g_hh + ((size_t)e * T_TOK + r1) * H_DIM;
        bool v0 = r0 < cnt, v1 = r1 < cnt;
#pragma unroll
        for (int fn = 0; fn < 4; fn++) {
            int c = n0 + wn * 32 + fn * 8 + 2 * tg;
            if (v0) {
                float ga = accg[fm][fn][0], gb = accg[fm][fn][1];
                float oa = 0.5f * ga * (1.0f + erff(ga * 0.70710678118654752f))
                         * accv[fm][fn][0];
                float ob = 0.5f * gb * (1.0f + erff(gb * 0.70710678118654752f))
                         * accv[fm][fn][1];
                *(__half2*)(h0 + c) = __floats2half2_rn(oa, ob);
            }
            if (v1) {
                float ga = accg[fm][fn][2], gb = accg[fm][fn][3];
                float oa = 0.5f * ga * (1.0f + erff(ga * 0.70710678118654752f))
                         * accv[fm][fn][2];
                float ob = 0.5f * gb * (1.0f + erff(gb * 0.70710678118654752f))
                         * accv[fm][fn][3];
                *(__half2*)(h1 + c) = __floats2half2_rn(oa, ob);
            }
        }
    }
}

// ---------------------------------------------------------------------------
// Stage 2: y = h @ (Wo*scale)^T, split-K x2 (separate buffers, deterministic).
// Block 128m x 64n. blockIdx.z = e*2 + khalf. Grid (16, 12, 16). fp16 out.
// ---------------------------------------------------------------------------
__global__ __launch_bounds__(256, 2) void gemm2_tc()
{
    extern __shared__ __half smh[];
    const int e     = blockIdx.z >> 1;
    const int kh    = blockIdx.z & 1;
    const int cnt   = g_count[e];
    const int m0    = blockIdx.x * 128;
    if (m0 >= cnt) return;
    const int n0    = blockIdx.y * 64;
    const int kbase = kh * (H_DIM / 2);

    const int tid  = threadIdx.x;
    const int lane = tid & 31;
    const int wid  = tid >> 5;
    const int wm   = wid >> 1;
    const int wn   = wid & 1;
    const int g    = lane >> 2;
    const int tg   = lane & 3;

    const int seg = tid & 7;
    const int rr  = tid >> 3;         // 0..31
    const uint32_t sb = sm_addr(smh);
    const size_t ewo = (size_t)e * D_DIM * H_DIM;

    const __half* asrc[4]; uint32_t asz[4]; uint32_t adst[4];
#pragma unroll
    for (int i = 0; i < 4; i++) {
        int r    = rr + 32 * i;
        int slot = m0 + r;
        bool v   = slot < cnt;
        asrc[i]  = g_hh + ((size_t)e * T_TOK + (v ? slot : 0)) * H_DIM
                 + kbase + seg * 8;
        asz[i]   = v ? 16u : 0u;
        adst[i]  = (uint32_t)(r * PH + seg * 8) * 2u;
    }
    const __half* bsrc[2]; uint32_t bdst[2];
#pragma unroll
    for (int i = 0; i < 2; i++) {
        int r   = rr + 32 * i;        // 0..63
        bsrc[i] = g_woh + ewo + (size_t)(n0 + r) * H_DIM + kbase + seg * 8;
        bdst[i] = (uint32_t)(r * PH + seg * 8) * 2u;
    }

#define G2_LOAD(slot, k0) do {                                                   \
    uint32_t _b = sb + (uint32_t)(slot) * BUF2B;                                  \
    _Pragma("unroll")                                                             \
    for (int i = 0; i < 4; i++)                                                   \
        CP16Z(_b + adst[i], (asrc[i] + (k0)), asz[i]);                            \
    _Pragma("unroll")                                                             \
    for (int i = 0; i < 2; i++)                                                   \
        CP16(_b + BOFFB + bdst[i], (bsrc[i] + (k0)));                             \
    CP_COMMIT();                                                                  \
} while (0)

    const uint32_t aoff = (uint32_t)((wm * 32 + (lane & 15)) * PH
                                     + ((lane >> 4) * 8)) * 2u;
    const uint32_t boff = (uint32_t)((wn * 32 + ((lane >> 4) * 8) + (lane & 7)) * PH
                                     + (((lane >> 3) & 1) * 8)) * 2u;

    float acc[2][4][4] = {};

    const int NIT = (H_DIM / 2) / KC;   // 24
    G2_LOAD(0, 0);
    G2_LOAD(1, KC);

    int slot = 0;
#pragma unroll 1
    for (int it = 0; it < NIT; ++it) {
        if (it < NIT - 1) CP_WAIT1(); else CP_WAIT0();
        __syncthreads();

        if (it + 2 < NIT) {
            int ns = slot + 2; if (ns >= STAGES) ns -= STAGES;
            G2_LOAD(ns, (it + 2) * KC);
        }

        const uint32_t ba = sb + (uint32_t)slot * BUF2B;
        const uint32_t Aa = ba + aoff;
        const uint32_t Ba = ba + BOFFB + boff;
#pragma unroll
        for (int ks = 0; ks < 4; ks++) {
            const uint32_t kb = ks * 32;
            uint32_t a[2][4];
#pragma unroll
            for (int fm = 0; fm < 2; fm++)
                LDSM4(a[fm], Aa + fm * (16 * ROWB) + kb);
#pragma unroll
            for (int fp = 0; fp < 2; fp++) {
                uint32_t b[4];
                LDSM4(b, Ba + fp * (16 * ROWB) + kb);
#pragma unroll
                for (int fm = 0; fm < 2; fm++) {
                    MMA_F16(acc[fm][2 * fp],     a[fm], (b + 0));
                    MMA_F16(acc[fm][2 * fp + 1], a[fm], (b + 2));
                }
            }
        }
        slot++; if (slot >= STAGES) slot -= STAGES;
    }

    __half* ybuf = kh ? g_y2 : g_y;
#pragma unroll
    for (int fm = 0; fm < 2; fm++) {
        int r0 = m0 + wm * 32 + fm * 16 + g;
        int r1 = r0 + 8;
        __half* y0 = ybuf + ((size_t)e * T_TOK + r0) * D_DIM;
        __half* y1 = ybuf + ((size_t)e * T_TOK + r1) * D_DIM;
        bool v0 = r0 < cnt, v1 = r1 < cnt;
#pragma unroll
        for (int fn = 0; fn < 4; fn++) {
            int c = n0 + wn * 32 + fn * 8 + 2 * tg;
            if (v0) *(__half2*)(y0 + c) =
                __floats2half2_rn(acc[fm][fn][0], acc[fm][fn][1]);
            if (v1) *(__half2*)(y1 + c) =
                __floats2half2_rn(acc[fm][fn][2], acc[fm][fn][3]);
        }
    }
}

// ---------------------------------------------------------------------------
// Combine -> d_out. 4 elements per thread (uint2 loads = 4 halves per buffer,
// two float2 stores). fp32 accumulation, single deterministic write/element.
// ---------------------------------------------------------------------------
__global__ void combine_kernel(const float* __restrict__ comb,
                               float* __restrict__ out)
{
    int idx = blockIdx.x * blockDim.x + threadIdx.x;   // over T*D/4
    if (idx >= T_TOK * (D_DIM / 4)) return;
    int t  = idx / (D_DIM / 4);
    int d4 = idx - t * (D_DIM / 4);
    float4 acc = make_float4(0.0f, 0.0f, 0.0f, 0.0f);
    int np = g_np[t];
    for (int j = 0; j < np; j++) {
        int e = g_te[t * E_EXP + j];
        int s = g_ts[t * E_EXP + j];
        size_t o = ((size_t)e * T_TOK + s) * (D_DIM / 4) + d4;
        uint2 ua = *((const uint2*)g_y  + o);
        uint2 ub = *((const uint2*)g_y2 + o);
        float2 a0 = __half22float2(*(const __half2*)&ua.x);
        float2 a1 = __half22float2(*(const __half2*)&ua.y);
        float2 b0 = __half22float2(*(const __half2*)&ub.x);
        float2 b1 = __half22float2(*(const __half2*)&ub.y);
        float  w  = comb[t * E_EXP + e];
        acc.x += w * (a0.x + b0.x);
        acc.y += w * (a0.y + b0.y);
        acc.z += w * (a1.x + b1.x);
        acc.w += w * (a1.y + b1.y);
    }
    ((float2*)out)[idx * 2]     = make_float2(acc.x, acc.y);
    ((float2*)out)[idx * 2 + 1] = make_float2(acc.z, acc.w);
}

// ---------------------------------------------------------------------------
// Launch (R14 skeleton, byte-identical ordering). Side stream: zero+build
// overlap cvt_main; Wo cvt overlaps gemm1. Full-width GEMMs.
// ---------------------------------------------------------------------------
extern "C" void kernel_launch(void* const* d_in, const int* in_sizes, int n_in,
                              void* d_out, int out_size)
{
    const float* tokens = (const float*)d_in[0];
    const float* disp   = (const float*)d_in[1];
    const float* comb   = (const float*)d_in[2];
    const float* Wg     = (const float*)d_in[3];
    const float* Wv     = (const float*)d_in[4];
    const float* Wo     = (const float*)d_in[5];
    const float* scale  = (const float*)d_in[6];
    float* out = (float*)d_out;

    static cudaStream_t s2 = nullptr;
    static cudaEvent_t evS = nullptr, evB = nullptr, evF = nullptr, evJ = nullptr;
    if (!s2) {
        cudaStreamCreateWithFlags(&s2, cudaStreamNonBlocking);
        cudaEventCreateWithFlags(&evS, cudaEventDisableTiming);
        cudaEventCreateWithFlags(&evB, cudaEventDisableTiming);
        cudaEventCreateWithFlags(&evF, cudaEventDisableTiming);
        cudaEventCreateWithFlags(&evJ, cudaEventDisableTiming);
        cudaFuncSetAttribute(gemm1_tc, cudaFuncAttributeMaxDynamicSharedMemorySize, SMEM1);
        cudaFuncSetAttribute(gemm2_tc, cudaFuncAttributeMaxDynamicSharedMemorySize, SMEM2);
    }

    __half* xh;  cudaGetSymbolAddress((void**)&xh,  g_xh);
    __half* wgh; cudaGetSymbolAddress((void**)&wgh, g_wgh);
    __half* wvh; cudaGetSymbolAddress((void**)&wvh, g_wvh);
    __half* woh; cudaGetSymbolAddress((void**)&woh, g_woh);

    // Fork at start: side stream runs routing build while main runs cvt_main.
    cudaEventRecord(evS, 0);
    cudaStreamWaitEvent(s2, evS, 0);
    zero_counts_kernel<<<1, 32, 0, s2>>>();
    build_kernel<<<(T_TOK + 255) / 256, 256, 0, s2>>>(disp);
    cudaEventRecord(evB, s2);

    cvt_main_kernel<<<(NTOT4 / 2 + 255) / 256, 256>>>(
        (const float4*)tokens, (const float4*)Wg, (const float4*)Wv,
        (uint2*)xh, (uint2*)wgh, (uint2*)wvh);

    // Wo conversion on side stream (after build), overlapping gemm1.
    cudaEventRecord(evF, 0);
    cudaStreamWaitEvent(s2, evF, 0);
    cvt_wo_kernel<<<(W4 / 2 + 255) / 256, 256, 0, s2>>>(
        (const float4*)Wo, scale, (uint2*)woh);
    cudaEventRecord(evJ, s2);

    // gemm1 needs build (g_tok/g_count) + cvt_main.
    cudaStreamWaitEvent(0, evB, 0);
    dim3 g1(T_TOK / 128, H_DIM / 64, E_EXP);        // (16, 48, 8)
    gemm1_tc<<<g1, 256, SMEM1>>>();

    // gemm2 needs woh.
    cudaStreamWaitEvent(0, evJ, 0);
    dim3 g2(T_TOK / 128, D_DIM / 64, 2 * E_EXP);    // (16, 12, 16) split-K
    gemm2_tc<<<g2, 256, SMEM2>>>();

    combine_kernel<<<(T_TOK * D_DIM / 4 + 255) / 256, 256>>>(comb, out);
}